// round 14
// baseline (speedup 1.0000x reference)
#include <cuda_runtime.h>
#include <math.h>
#include <complex>

// ---------------------------------------------------------------------------
// Problem constants / scratch
// ---------------------------------------------------------------------------
#define MAX_E 256000

// Flat CG storage, row-major (a*(2l2+1)+b)*(2l3+1)+c, 11 paths concatenated.
struct CGParams { float cg[363]; };

#define O000 0
#define O110 1
#define O220 10
#define O011 35
#define O101 44
#define O121 53
#define O211 98
#define O022 143
#define O112 168
#define O202 213
#define O222 238

// Per-edge selfmix scratch, padded to 12 floats/edge for float4 access.
__device__ float4 g_Za[MAX_E * 3];
__device__ float4 g_Zb[MAX_E * 3];

// sqrt(2*l3+1)/sqrt(npaths(l3))
#define CN0 0.57735026918962576f
#define CN1 0.86602540378443865f
#define CN2 1.11803398874989485f

__device__ __forceinline__ int muv(int i, int L) { return i < L ? L - i : i - L; }

// z[c] += w * sum_{a,b} cg[a,b,c] * x[a] * y[b], compile-time sparsity guard
// (real-CG nonzeros satisfy mu_c in {mu_a+mu_b, |mu_a-mu_b|}).
template <int L1, int L2, int L3>
__device__ __forceinline__ void tp_acc(const float* x, const float* y,
                                       const float* cg, float w, float* z) {
    float zp[2 * L3 + 1];
#pragma unroll
    for (int c = 0; c < 2 * L3 + 1; ++c) zp[c] = 0.f;
#pragma unroll
    for (int a = 0; a < 2 * L1 + 1; ++a) {
#pragma unroll
        for (int b = 0; b < 2 * L2 + 1; ++b) {
            float p = x[a] * y[b];
#pragma unroll
            for (int c = 0; c < 2 * L3 + 1; ++c) {
                const int mua = muv(a, L1), mub = muv(b, L2), muc = muv(c, L3);
                const int dmu = mua > mub ? mua - mub : mub - mua;
                if (muc == mua + mub || muc == dmu)
                    zp[c] = fmaf(cg[(a * (2 * L2 + 1) + b) * (2 * L3 + 1) + c], p, zp[c]);
            }
        }
    }
#pragma unroll
    for (int c = 0; c < 2 * L3 + 1; ++c) z[c] = fmaf(w, zp[c], z[c]);
}

// Selfmix on one 9-vector (cin = 1)
__device__ __forceinline__ void selfmix1(const float* Y, const float* cg,
                                         const float* w0, const float* w1,
                                         const float* w2, float b0,
                                         const float* k, float* Z) {
#pragma unroll
    for (int m = 0; m < 9; ++m) Z[m] = 0.f;
    tp_acc<0, 0, 0>(Y,     Y,     cg + O000, w0[0] * CN0, Z);
    tp_acc<1, 1, 0>(Y + 1, Y + 1, cg + O110, w0[1] * CN0, Z);
    tp_acc<2, 2, 0>(Y + 4, Y + 4, cg + O220, w0[2] * CN0, Z);
    tp_acc<0, 1, 1>(Y,     Y + 1, cg + O011, w1[0] * CN1, Z + 1);
    tp_acc<1, 0, 1>(Y + 1, Y,     cg + O101, w1[1] * CN1, Z + 1);
    tp_acc<1, 2, 1>(Y + 1, Y + 4, cg + O121, w1[2] * CN1, Z + 1);
    tp_acc<2, 1, 1>(Y + 4, Y + 1, cg + O211, w1[3] * CN1, Z + 1);
    tp_acc<0, 2, 2>(Y,     Y + 4, cg + O022, w2[0] * CN2, Z + 4);
    tp_acc<1, 1, 2>(Y + 1, Y + 1, cg + O112, w2[1] * CN2, Z + 4);
    tp_acc<2, 0, 2>(Y + 4, Y,     cg + O202, w2[2] * CN2, Z + 4);
    tp_acc<2, 2, 2>(Y + 4, Y + 4, cg + O222, w2[3] * CN2, Z + 4);
    Z[0] += b0 + k[0] * Y[0];
#pragma unroll
    for (int m = 1; m < 4; ++m) Z[m] += k[1] * Y[m];
#pragma unroll
    for (int m = 4; m < 9; ++m) Z[m] += k[2] * Y[m];
}

// ---------------------------------------------------------------------------
// Kernel 1: per-edge selfmix of Y_edge, both branches
// ---------------------------------------------------------------------------
__global__ void zprep_kernel(const float* __restrict__ Y_edge,
                             const float* w0a, const float* w1a, const float* w2a,
                             const float* b0a, const float* ka,
                             const float* w0b, const float* w1b, const float* w2b,
                             const float* b0b, const float* kb,
                             int E, CGParams P) {
    int e = blockIdx.x * blockDim.x + threadIdx.x;
    if (e >= E) return;
    float Y[9];
#pragma unroll
    for (int m = 0; m < 9; ++m) Y[m] = Y_edge[(size_t)e * 9 + m];

    float Z[9];
    {
        float w0[3] = {w0a[0], w0a[1], w0a[2]};
        float w1[4] = {w1a[0], w1a[1], w1a[2], w1a[3]};
        float w2[4] = {w2a[0], w2a[1], w2a[2], w2a[3]};
        float kk[3] = {ka[0], ka[1], ka[2]};
        selfmix1(Y, P.cg, w0, w1, w2, b0a[0], kk, Z);
        g_Za[(size_t)e * 3 + 0] = make_float4(Z[0], Z[1], Z[2], Z[3]);
        g_Za[(size_t)e * 3 + 1] = make_float4(Z[4], Z[5], Z[6], Z[7]);
        g_Za[(size_t)e * 3 + 2] = make_float4(Z[8], 0.f, 0.f, 0.f);
    }
    {
        float w0[3] = {w0b[0], w0b[1], w0b[2]};
        float w1[4] = {w1b[0], w1b[1], w1b[2], w1b[3]};
        float w2[4] = {w2b[0], w2b[1], w2b[2], w2b[3]};
        float kk[3] = {kb[0], kb[1], kb[2]};
        selfmix1(Y, P.cg, w0, w1, w2, b0b[0], kk, Z);
        g_Zb[(size_t)e * 3 + 0] = make_float4(Z[0], Z[1], Z[2], Z[3]);
        g_Zb[(size_t)e * 3 + 1] = make_float4(Z[4], Z[5], Z[6], Z[7]);
        g_Zb[(size_t)e * 3 + 2] = make_float4(Z[8], 0.f, 0.f, 0.f);
    }
}

// ---------------------------------------------------------------------------
// f32x2 packed helpers (PTX-only; ptxas never auto-fuses FFMA2)
// ---------------------------------------------------------------------------
__device__ __forceinline__ unsigned long long pk2(float lo, float hi) {
    unsigned long long r;
    asm("mov.b64 %0, {%1, %2};" : "=l"(r) : "f"(lo), "f"(hi));
    return r;
}
__device__ __forceinline__ void upk2(float& lo, float& hi, unsigned long long v) {
    asm("mov.b64 {%0, %1}, %2;" : "=f"(lo), "=f"(hi) : "l"(v));
}
__device__ __forceinline__ unsigned long long fma2(unsigned long long a,
                                                   unsigned long long b,
                                                   unsigned long long c) {
    unsigned long long d;
    asm("fma.rn.f32x2 %0, %1, %2, %3;" : "=l"(d) : "l"(a), "l"(b), "l"(c));
    return d;
}

// ---------------------------------------------------------------------------
// Kernel 2: fused main edge kernel. Warp = EPW edges, lane = channel.
// R10 structure; ONLY change: matvec uses padded smem weights + fma.rn.f32x2.
// smem: WdA [32][32][4] 16384 B + WdB [32][32][12] 49152 B + CG 1472 B +
//       staging 4608 B = 71616 B; 3 blocks/SM (12 warps), 170-reg budget.
// ---------------------------------------------------------------------------
#define EPW    4
#define TPB    128
#define NWARPS 4
#define SM_WDA 0
#define SM_WDB 4096
#define SM_CG  16384
#define SM_ST  16752                        // 16B-aligned staging base
#define SM_FLOATS (SM_ST + NWARPS * 288)    // 17904 floats = 71616 B

__device__ __forceinline__ void red_add_v4(float4* addr, float4 v) {
    asm volatile("red.global.add.v4.f32 [%0], {%1,%2,%3,%4};"
                 :: "l"(addr), "f"(v.x), "f"(v.y), "f"(v.z), "f"(v.w)
                 : "memory");
}

__global__ void __launch_bounds__(TPB, 3)
edge_kernel(const float* __restrict__ nodes_snd, const int* __restrict__ edge_ind,
            const float* __restrict__ dist,
            const float* __restrict__ WdA, const float* __restrict__ bdA,
            const float* __restrict__ WdB, const float* __restrict__ bdB,
            const float* __restrict__ cmWa, const float* __restrict__ cmba,
            const float* __restrict__ cmWb, const float* __restrict__ cmbb,
            float* __restrict__ out, int E, CGParams P) {
    extern __shared__ float sm[];
    float* sWdA = sm + SM_WDA;   // [32 f][32 c][4]  (pad lane = 0)
    float* sWdB = sm + SM_WDB;   // [32 f][32 c][12] (pad lane = 0)
    float* sCG  = sm + SM_CG;    // [363]
    float* sSt  = sm + SM_ST;    // [NWARPS][288]

    const int tid = threadIdx.x, lane = tid & 31, warp = tid >> 5;

    // Stage padded weights
    for (int i = tid; i < 4096; i += TPB) {
        int f = i >> 7, j = i & 127, c = j >> 2, l = j & 3;
        sWdA[i] = (l < 3) ? WdA[f * 96 + c * 3 + l] : 0.f;
    }
    for (int i = tid; i < 12288; i += TPB) {
        int f = i / 384, j = i % 384, c = j / 12, jj = j % 12;
        sWdB[i] = (jj < 11) ? WdB[f * 352 + c * 11 + jj] : 0.f;
    }
    for (int i = tid; i < 363; i += TPB) sCG[i] = P.cg[i];

    // Per-lane (channel) constants
    float cma[3], cmbv[3];
#pragma unroll
    for (int l = 0; l < 3; ++l) {
        cma[l]  = cmWa[l * 32 + lane];
        cmbv[l] = cmWb[l * 32 + lane];
    }
    const float cba = cmba[lane], cbb = cmbb[lane];
    __syncthreads();

    const int e0 = (blockIdx.x * NWARPS + warp) * EPW;
    if (e0 >= E) return;

    float d[EPW];
#pragma unroll
    for (int k = 0; k < EPW; ++k) {
        int e = e0 + k;
        d[k] = (e < E) ? dist[(size_t)e * 32 + lane] : 0.f;
    }

    // Packed accumulators, biases pre-folded (pad halves init 0)
    unsigned long long accA2[EPW][2], accB2[EPW][6];
    {
        float bA0 = bdA[lane * 3 + 0], bA1 = bdA[lane * 3 + 1], bA2 = bdA[lane * 3 + 2];
        unsigned long long a0 = pk2(bA0, bA1), a1 = pk2(bA2, 0.f);
        float bB[11];
#pragma unroll
        for (int j = 0; j < 11; ++j) bB[j] = bdB[lane * 11 + j];
        unsigned long long b0 = pk2(bB[0], bB[1]), b1 = pk2(bB[2], bB[3]);
        unsigned long long b2 = pk2(bB[4], bB[5]), b3 = pk2(bB[6], bB[7]);
        unsigned long long b4 = pk2(bB[8], bB[9]), b5 = pk2(bB[10], 0.f);
#pragma unroll
        for (int k = 0; k < EPW; ++k) {
            accA2[k][0] = a0; accA2[k][1] = a1;
            accB2[k][0] = b0; accB2[k][1] = b1; accB2[k][2] = b2;
            accB2[k][3] = b3; accB2[k][4] = b4; accB2[k][5] = b5;
        }
    }

    // dist @ Wd with packed f32x2 FMA: per f, 4 LDS.128 (as ulonglong2) +
    // 4 shfl + 4 dup-packs + 32 FFMA2 (vs 14 LDS + 4 shfl + 56 FFMA).
#pragma unroll 4
    for (int f = 0; f < 32; ++f) {
        ulonglong2 av  = *reinterpret_cast<const ulonglong2*>(sWdA + f * 128 + lane * 4);
        const ulonglong2* wb = reinterpret_cast<const ulonglong2*>(sWdB + f * 384 + lane * 12);
        ulonglong2 bv0 = wb[0], bv1 = wb[1], bv2 = wb[2];
#pragma unroll
        for (int k = 0; k < EPW; ++k) {
            float df = __shfl_sync(0xffffffffu, d[k], f);
            unsigned long long dp = pk2(df, df);
            accA2[k][0] = fma2(dp, av.x,  accA2[k][0]);
            accA2[k][1] = fma2(dp, av.y,  accA2[k][1]);
            accB2[k][0] = fma2(dp, bv0.x, accB2[k][0]);
            accB2[k][1] = fma2(dp, bv0.y, accB2[k][1]);
            accB2[k][2] = fma2(dp, bv1.x, accB2[k][2]);
            accB2[k][3] = fma2(dp, bv1.y, accB2[k][3]);
            accB2[k][4] = fma2(dp, bv2.x, accB2[k][4]);
            accB2[k][5] = fma2(dp, bv2.y, accB2[k][5]);
        }
    }

    float*  st  = sSt + warp * 288;
    float4* st4 = reinterpret_cast<float4*>(st);

#pragma unroll 1
    for (int k = 0; k < EPW; ++k) {
        const int e = e0 + k;
        if (e >= E) break;
        const int2 ei = reinterpret_cast<const int2*>(edge_ind)[e];
        const int snd = ei.x, rcv = ei.y;

        // Cooperative coalesced node-row load (1152 B) -> smem -> per-lane read
        const float4* nb4 = reinterpret_cast<const float4*>(
            nodes_snd + (size_t)snd * 288);
        st4[lane]      = nb4[lane];
        st4[32 + lane] = nb4[32 + lane];
        if (lane < 8) st4[64 + lane] = nb4[64 + lane];
        __syncwarp();
        float n[9];
#pragma unroll
        for (int m = 0; m < 9; ++m) n[m] = st[lane * 9 + m];
        __syncwarp();

        // Uniform vector loads of selfmix scratch (lane-invariant broadcast)
        float Za[9], Zb[9];
        {
            float4 z0 = g_Za[(size_t)e * 3 + 0];
            float4 z1 = g_Za[(size_t)e * 3 + 1];
            float4 z2 = g_Za[(size_t)e * 3 + 2];
            Za[0] = z0.x; Za[1] = z0.y; Za[2] = z0.z; Za[3] = z0.w;
            Za[4] = z1.x; Za[5] = z1.y; Za[6] = z1.z; Za[7] = z1.w;
            Za[8] = z2.x;
            z0 = g_Zb[(size_t)e * 3 + 0];
            z1 = g_Zb[(size_t)e * 3 + 1];
            z2 = g_Zb[(size_t)e * 3 + 2];
            Zb[0] = z0.x; Zb[1] = z0.y; Zb[2] = z0.z; Zb[3] = z0.w;
            Zb[4] = z1.x; Zb[5] = z1.y; Zb[6] = z1.z; Zb[7] = z1.w;
            Zb[8] = z2.x;
        }

        // Channel mix (cin = 1)
        float Ya[9], Yb[9];
        Ya[0] = fmaf(Za[0], cma[0], cba);
        Yb[0] = fmaf(Zb[0], cmbv[0], cbb);
#pragma unroll
        for (int m = 1; m < 4; ++m) { Ya[m] = Za[m] * cma[1]; Yb[m] = Zb[m] * cmbv[1]; }
#pragma unroll
        for (int m = 4; m < 9; ++m) { Ya[m] = Za[m] * cma[2]; Yb[m] = Zb[m] * cmbv[2]; }

        // Unpack this edge's matvec results
        float aw0, aw1, aw2, dum;
        upk2(aw0, aw1, accA2[k][0]);
        upk2(aw2, dum, accA2[k][1]);
        float wb[11];
        upk2(wb[0], wb[1], accB2[k][0]);
        upk2(wb[2], wb[3], accB2[k][1]);
        upk2(wb[4], wb[5], accB2[k][2]);
        upk2(wb[6], wb[7], accB2[k][3]);
        upk2(wb[8], wb[9], accB2[k][4]);
        upk2(wb[10], dum, accB2[k][5]);

        float wa[3] = {aw0 * n[0], aw1 * n[0], aw2 * n[0]};

        // a-branch message
        float msg[9];
        msg[0] = wa[0] * Ya[0];
#pragma unroll
        for (int m = 1; m < 4; ++m) msg[m] = wa[1] * Ya[m];
#pragma unroll
        for (int m = 4; m < 9; ++m) msg[m] = wa[2] * Ya[m];

        // b-branch: pair_mix(neighbors, Yb, wb), CG from smem
        tp_acc<0, 0, 0>(n,     Yb,     sCG + O000, wb[0]  * CN0, msg);
        tp_acc<1, 1, 0>(n + 1, Yb + 1, sCG + O110, wb[1]  * CN0, msg);
        tp_acc<2, 2, 0>(n + 4, Yb + 4, sCG + O220, wb[2]  * CN0, msg);
        tp_acc<0, 1, 1>(n,     Yb + 1, sCG + O011, wb[3]  * CN1, msg + 1);
        tp_acc<1, 0, 1>(n + 1, Yb,     sCG + O101, wb[4]  * CN1, msg + 1);
        tp_acc<1, 2, 1>(n + 1, Yb + 4, sCG + O121, wb[5]  * CN1, msg + 1);
        tp_acc<2, 1, 1>(n + 4, Yb + 1, sCG + O211, wb[6]  * CN1, msg + 1);
        tp_acc<0, 2, 2>(n,     Yb + 4, sCG + O022, wb[7]  * CN2, msg + 4);
        tp_acc<1, 1, 2>(n + 1, Yb + 1, sCG + O112, wb[8]  * CN2, msg + 4);
        tp_acc<2, 0, 2>(n + 4, Yb,     sCG + O202, wb[9]  * CN2, msg + 4);
        tp_acc<2, 2, 2>(n + 4, Yb + 4, sCG + O222, wb[10] * CN2, msg + 4);

        // Transpose via smem, then coalesced float4 vector atomics.
#pragma unroll
        for (int m = 0; m < 9; ++m) st[lane * 9 + m] = msg[m];
        __syncwarp();
        float4* dst = reinterpret_cast<float4*>(out + (size_t)rcv * 288);
        red_add_v4(dst + lane,      st4[lane]);
        red_add_v4(dst + 32 + lane, st4[32 + lane]);
        if (lane < 8) red_add_v4(dst + 64 + lane, st4[64 + lane]);
        __syncwarp();
    }
}

// ---------------------------------------------------------------------------
// Host: exact double-precision port of the reference real-CG construction
// ---------------------------------------------------------------------------
typedef std::complex<double> cd;

static double factd(int n) { double r = 1.0; for (int i = 2; i <= n; ++i) r *= i; return r; }

static double w3j_h(int j1, int j2, int j3, int m1, int m2, int m3) {
    if (m1 + m2 + m3 != 0) return 0.0;
    int lo = j1 - j2; if (lo < 0) lo = -lo;
    if (j3 < lo || j3 > j1 + j2) return 0.0;
    int t1 = j2 - m1 - j3, t2 = j1 + m2 - j3, t3 = j1 + j2 - j3;
    int t4 = j1 - m1, t5 = j2 + m2;
    int tmin = 0; if (t1 > tmin) tmin = t1; if (t2 > tmin) tmin = t2;
    int tmax = t3; if (t4 < tmax) tmax = t4; if (t5 < tmax) tmax = t5;
    double s = 0.0;
    for (int t = tmin; t <= tmax; ++t)
        s += ((t & 1) ? -1.0 : 1.0) /
             (factd(t) * factd(t - t1) * factd(t - t2) *
              factd(t3 - t) * factd(t4 - t) * factd(t5 - t));
    double delta = factd(j1 + j2 - j3) * factd(j1 - j2 + j3) *
                   factd(-j1 + j2 + j3) / factd(j1 + j2 + j3 + 1);
    double norm = sqrt(delta * factd(j1 + m1) * factd(j1 - m1) *
                       factd(j2 + m2) * factd(j2 - m2) *
                       factd(j3 + m3) * factd(j3 - m3));
    int e = j1 - j2 - m3;
    double sgn = (((e % 2) + 2) % 2) ? -1.0 : 1.0;
    return sgn * norm * s;
}

static void u_real_h(int l, cd U[5][5]) {
    for (int i = 0; i < 5; ++i)
        for (int j = 0; j < 5; ++j) U[i][j] = 0.0;
    U[l][l] = 1.0;
    double s2 = 1.0 / sqrt(2.0);
    for (int m = 1; m <= l; ++m) {
        double sg = (m & 1) ? -1.0 : 1.0;
        U[l + m][l + m] = sg * s2;
        U[l + m][l - m] = s2;
        U[l - m][l + m] = cd(0.0, -1.0) * sg * s2;
        U[l - m][l - m] = cd(0.0, 1.0) * s2;
    }
}

static void real_cg_h(int l1, int l2, int l3, float* out) {
    int d1 = 2 * l1 + 1, d2 = 2 * l2 + 1, d3 = 2 * l3 + 1;
    static cd W[5][5][5];
    for (int a = 0; a < 5; ++a)
        for (int b = 0; b < 5; ++b)
            for (int c = 0; c < 5; ++c) W[a][b][c] = 0.0;
    for (int m1 = -l1; m1 <= l1; ++m1)
        for (int m2 = -l2; m2 <= l2; ++m2) {
            int m3 = -(m1 + m2);
            if (m3 >= -l3 && m3 <= l3)
                W[l1 + m1][l2 + m2][l3 + m3] = w3j_h(l1, l2, l3, m1, m2, m3);
        }
    cd U1[5][5], U2[5][5], U3[5][5];
    u_real_h(l1, U1); u_real_h(l2, U2); u_real_h(l3, U3);
    static cd T[5][5][5];
    double mxr = 0.0, mxi = 0.0;
    for (int a = 0; a < d1; ++a)
        for (int b = 0; b < d2; ++b)
            for (int c = 0; c < d3; ++c) {
                cd s = 0.0;
                for (int m = 0; m < d1; ++m) {
                    if (U1[a][m] == cd(0.0)) continue;
                    for (int n = 0; n < d2; ++n) {
                        if (U2[b][n] == cd(0.0)) continue;
                        for (int o = 0; o < d3; ++o)
                            s += U1[a][m] * U2[b][n] * U3[c][o] * W[m][n][o];
                    }
                }
                T[a][b][c] = s;
                if (fabs(s.real()) > mxr) mxr = fabs(s.real());
                if (fabs(s.imag()) > mxi) mxi = fabs(s.imag());
            }
    bool useRe = (mxr >= mxi);
    for (int a = 0; a < d1; ++a)
        for (int b = 0; b < d2; ++b)
            for (int c = 0; c < d3; ++c)
                out[(a * d2 + b) * d3 + c] =
                    (float)(useRe ? T[a][b][c].real() : T[a][b][c].imag());
}

static void build_cg(CGParams* P) {
    const int pl[11][3] = {{0,0,0},{1,1,0},{2,2,0},
                           {0,1,1},{1,0,1},{1,2,1},{2,1,1},
                           {0,2,2},{1,1,2},{2,0,2},{2,2,2}};
    int off = 0;
    for (int p = 0; p < 11; ++p) {
        int l1 = pl[p][0], l2 = pl[p][1], l3 = pl[p][2];
        real_cg_h(l1, l2, l3, P->cg + off);
        off += (2 * l1 + 1) * (2 * l2 + 1) * (2 * l3 + 1);
    }
}

// ---------------------------------------------------------------------------
// kernel_launch
// ---------------------------------------------------------------------------
extern "C" void kernel_launch(void* const* d_in, const int* in_sizes, int n_in,
                              void* d_out, int out_size) {
    CGParams P;
    build_cg(&P);

    const float* nodes_rec = (const float*)d_in[0];
    const float* nodes_snd = (const float*)d_in[1];
    const int*   edge_ind  = (const int*)d_in[2];
    const float* Y_edge    = (const float*)d_in[3];
    const float* dist      = (const float*)d_in[4];
    const int E = in_sizes[2] / 2;

    // Detect parameter ordering: signature order has Wd_a (3072) at index 12.
    int iA0, iB0, iWdA, ibdA, iWdB, ibdB;
    if (in_sizes[12] >= 3000) {  // signature order
        iA0 = 5;  iWdA = 12; ibdA = 13;
        iB0 = 14; iWdB = 21; ibdB = 22;
    } else {                     // dict order
        iA0 = 5;  iB0 = 12;
        iWdA = 19; ibdA = 20; iWdB = 21; ibdB = 22;
    }
    const float* sm_a_w0 = (const float*)d_in[iA0 + 0];
    const float* sm_a_w1 = (const float*)d_in[iA0 + 1];
    const float* sm_a_w2 = (const float*)d_in[iA0 + 2];
    const float* sm_a_b0 = (const float*)d_in[iA0 + 3];
    const float* sm_a_k  = (const float*)d_in[iA0 + 4];
    const float* cm_a_W  = (const float*)d_in[iA0 + 5];
    const float* cm_a_b  = (const float*)d_in[iA0 + 6];
    const float* sm_b_w0 = (const float*)d_in[iB0 + 0];
    const float* sm_b_w1 = (const float*)d_in[iB0 + 1];
    const float* sm_b_w2 = (const float*)d_in[iB0 + 2];
    const float* sm_b_b0 = (const float*)d_in[iB0 + 3];
    const float* sm_b_k  = (const float*)d_in[iB0 + 4];
    const float* cm_b_W  = (const float*)d_in[iB0 + 5];
    const float* cm_b_b  = (const float*)d_in[iB0 + 6];
    const float* Wd_a    = (const float*)d_in[iWdA];
    const float* bd_a    = (const float*)d_in[ibdA];
    const float* Wd_b    = (const float*)d_in[iWdB];
    const float* bd_b    = (const float*)d_in[ibdB];

    float* out = (float*)d_out;

    // out starts as nodes_rec; atomics accumulate messages on top.
    cudaMemcpyAsync(out, nodes_rec, (size_t)out_size * sizeof(float),
                    cudaMemcpyDeviceToDevice, 0);

    zprep_kernel<<<(E + 255) / 256, 256, 0, 0>>>(
        Y_edge, sm_a_w0, sm_a_w1, sm_a_w2, sm_a_b0, sm_a_k,
        sm_b_w0, sm_b_w1, sm_b_w2, sm_b_b0, sm_b_k, E, P);

    static bool attr_set = false;
    if (!attr_set) {
        cudaFuncSetAttribute(edge_kernel,
                             cudaFuncAttributeMaxDynamicSharedMemorySize,
                             SM_FLOATS * 4);
        attr_set = true;
    }
    int blocks = (E + NWARPS * EPW - 1) / (NWARPS * EPW);
    edge_kernel<<<blocks, TPB, SM_FLOATS * 4, 0>>>(
        nodes_snd, edge_ind, dist,
        Wd_a, bd_a, Wd_b, bd_b,
        cm_a_W, cm_a_b, cm_b_W, cm_b_b,
        out, E, P);
}

// round 15
// speedup vs baseline: 1.4885x; 1.4885x over previous
#include <cuda_runtime.h>
#include <math.h>

// ---------------------------------------------------------------------------
// Problem constants / scratch
// ---------------------------------------------------------------------------
#define MAX_E 256000

// Per-edge selfmix scratch, padded to 12 floats/edge for float4 access.
__device__ float4 g_Za[MAX_E * 3];
__device__ float4 g_Zb[MAX_E * 3];

// sqrt(2*l3+1)/sqrt(npaths(l3))
#define CN0 0.57735026918962576f
#define CN1 0.86602540378443865f
#define CN2 1.11803398874989485f

// ---------------------------------------------------------------------------
// Compile-time real Clebsch-Gordan construction (constexpr port of reference)
// ---------------------------------------------------------------------------
struct CD { double re, im; };
constexpr CD cmul(CD a, CD b) { return {a.re*b.re - a.im*b.im, a.re*b.im + a.im*b.re}; }
constexpr CD cmulr(CD a, double s) { return {a.re*s, a.im*s}; }
constexpr CD cadd(CD a, CD b) { return {a.re + b.re, a.im + b.im}; }

constexpr double cfabs(double x) { return x < 0 ? -x : x; }
constexpr double csqrt_(double x) {
    if (x <= 0.0) return 0.0;
    double g = x < 1.0 ? 1.0 : x;
    for (int i = 0; i < 200; ++i) g = 0.5 * (g + x / g);
    return g;
}
constexpr double factc(int n) { double r = 1.0; for (int i = 2; i <= n; ++i) r *= i; return r; }

constexpr double w3j_c(int j1, int j2, int j3, int m1, int m2, int m3) {
    if (m1 + m2 + m3 != 0) return 0.0;
    int lo = j1 - j2; if (lo < 0) lo = -lo;
    if (j3 < lo || j3 > j1 + j2) return 0.0;
    int t1 = j2 - m1 - j3, t2 = j1 + m2 - j3, t3 = j1 + j2 - j3;
    int t4 = j1 - m1, t5 = j2 + m2;
    int tmin = 0; if (t1 > tmin) tmin = t1; if (t2 > tmin) tmin = t2;
    int tmax = t3; if (t4 < tmax) tmax = t4; if (t5 < tmax) tmax = t5;
    double s = 0.0;
    for (int t = tmin; t <= tmax; ++t)
        s += ((t & 1) ? -1.0 : 1.0) /
             (factc(t) * factc(t - t1) * factc(t - t2) *
              factc(t3 - t) * factc(t4 - t) * factc(t5 - t));
    double delta = factc(j1 + j2 - j3) * factc(j1 - j2 + j3) *
                   factc(-j1 + j2 + j3) / factc(j1 + j2 + j3 + 1);
    double norm = csqrt_(delta * factc(j1 + m1) * factc(j1 - m1) *
                         factc(j2 + m2) * factc(j2 - m2) *
                         factc(j3 + m3) * factc(j3 - m3));
    int e = j1 - j2 - m3;
    double sgn = (((e % 2) + 2) % 2) ? -1.0 : 1.0;
    return sgn * norm * s;
}

struct U55 { CD u[5][5]; };
constexpr U55 u_real_c(int l) {
    U55 U{};
    U.u[l][l] = {1.0, 0.0};
    double s2 = 1.0 / csqrt_(2.0);
    for (int m = 1; m <= l; ++m) {
        double sg = (m & 1) ? -1.0 : 1.0;
        U.u[l + m][l + m] = {sg * s2, 0.0};
        U.u[l + m][l - m] = {s2, 0.0};
        U.u[l - m][l + m] = {0.0, -sg * s2};
        U.u[l - m][l - m] = {0.0, s2};
    }
    return U;
}

struct CGAll { float cg[363]; };
constexpr CGAll build_cg_c() {
    CGAll R{};
    const int pl[11][3] = {{0,0,0},{1,1,0},{2,2,0},
                           {0,1,1},{1,0,1},{1,2,1},{2,1,1},
                           {0,2,2},{1,1,2},{2,0,2},{2,2,2}};
    int off = 0;
    for (int p = 0; p < 11; ++p) {
        int l1 = pl[p][0], l2 = pl[p][1], l3 = pl[p][2];
        int d1 = 2*l1+1, d2 = 2*l2+1, d3 = 2*l3+1;
        double W[5][5][5] = {};
        for (int m1 = -l1; m1 <= l1; ++m1)
            for (int m2 = -l2; m2 <= l2; ++m2) {
                int m3 = -(m1 + m2);
                if (m3 >= -l3 && m3 <= l3)
                    W[l1 + m1][l2 + m2][l3 + m3] = w3j_c(l1, l2, l3, m1, m2, m3);
            }
        U55 U1 = u_real_c(l1), U2 = u_real_c(l2), U3 = u_real_c(l3);
        double Tre[5][5][5] = {}, Tim[5][5][5] = {};
        double mxr = 0.0, mxi = 0.0;
        for (int a = 0; a < d1; ++a)
            for (int b = 0; b < d2; ++b)
                for (int c = 0; c < d3; ++c) {
                    CD s = {0.0, 0.0};
                    for (int m = 0; m < d1; ++m) {
                        if (U1.u[a][m].re == 0.0 && U1.u[a][m].im == 0.0) continue;
                        for (int n = 0; n < d2; ++n) {
                            if (U2.u[b][n].re == 0.0 && U2.u[b][n].im == 0.0) continue;
                            for (int o = 0; o < d3; ++o) {
                                if (W[m][n][o] == 0.0) continue;
                                s = cadd(s, cmulr(cmul(cmul(U1.u[a][m], U2.u[b][n]),
                                                       U3.u[c][o]), W[m][n][o]));
                            }
                        }
                    }
                    Tre[a][b][c] = s.re; Tim[a][b][c] = s.im;
                    if (cfabs(s.re) > mxr) mxr = cfabs(s.re);
                    if (cfabs(s.im) > mxi) mxi = cfabs(s.im);
                }
        bool useRe = (mxr >= mxi);
        for (int a = 0; a < d1; ++a)
            for (int b = 0; b < d2; ++b)
                for (int c = 0; c < d3; ++c)
                    R.cg[off + (a * d2 + b) * d3 + c] =
                        (float)(useRe ? Tre[a][b][c] : Tim[a][b][c]);
        off += d1 * d2 * d3;
    }
    return R;
}
constexpr CGAll CGC = build_cg_c();

#define O000 0
#define O110 1
#define O220 10
#define O011 35
#define O101 44
#define O121 53
#define O211 98
#define O022 143
#define O112 168
#define O202 213
#define O222 238

// ---------------------------------------------------------------------------
// Tensor product with CG as compile-time immediates (exact-sparsity DCE).
// Each surviving term is a single FFMA with 32-bit immediate multiplier.
// ---------------------------------------------------------------------------
template <int OFF, int L2, int L3, int A, int B, int C = 0>
__device__ __forceinline__ void tp_cs(float p, float* zp) {
    if constexpr (C < 2 * L3 + 1) {
        constexpr float g = CGC.cg[OFF + (A * (2 * L2 + 1) + B) * (2 * L3 + 1) + C];
        if constexpr (g != 0.0f) zp[C] = fmaf(g, p, zp[C]);
        tp_cs<OFF, L2, L3, A, B, C + 1>(p, zp);
    }
}
template <int OFF, int L1, int L2, int L3, int A = 0, int B = 0>
__device__ __forceinline__ void tp_ab(const float* x, const float* y, float* zp) {
    if constexpr (B < 2 * L2 + 1) {
        float p = x[A] * y[B];
        tp_cs<OFF, L2, L3, A, B, 0>(p, zp);
        tp_ab<OFF, L1, L2, L3, A, B + 1>(x, y, zp);
    } else if constexpr (A + 1 < 2 * L1 + 1) {
        tp_ab<OFF, L1, L2, L3, A + 1, 0>(x, y, zp);
    }
}
template <int OFF, int L1, int L2, int L3>
__device__ __forceinline__ void tp_acc(const float* x, const float* y,
                                       float w, float* z) {
    float zp[2 * L3 + 1];
#pragma unroll
    for (int c = 0; c < 2 * L3 + 1; ++c) zp[c] = 0.f;
    tp_ab<OFF, L1, L2, L3, 0, 0>(x, y, zp);
#pragma unroll
    for (int c = 0; c < 2 * L3 + 1; ++c) z[c] = fmaf(w, zp[c], z[c]);
}

// Selfmix on one 9-vector (cin = 1)
__device__ __forceinline__ void selfmix1(const float* Y,
                                         const float* w0, const float* w1,
                                         const float* w2, float b0,
                                         const float* k, float* Z) {
#pragma unroll
    for (int m = 0; m < 9; ++m) Z[m] = 0.f;
    tp_acc<O000, 0, 0, 0>(Y,     Y,     w0[0] * CN0, Z);
    tp_acc<O110, 1, 1, 0>(Y + 1, Y + 1, w0[1] * CN0, Z);
    tp_acc<O220, 2, 2, 0>(Y + 4, Y + 4, w0[2] * CN0, Z);
    tp_acc<O011, 0, 1, 1>(Y,     Y + 1, w1[0] * CN1, Z + 1);
    tp_acc<O101, 1, 0, 1>(Y + 1, Y,     w1[1] * CN1, Z + 1);
    tp_acc<O121, 1, 2, 1>(Y + 1, Y + 4, w1[2] * CN1, Z + 1);
    tp_acc<O211, 2, 1, 1>(Y + 4, Y + 1, w1[3] * CN1, Z + 1);
    tp_acc<O022, 0, 2, 2>(Y,     Y + 4, w2[0] * CN2, Z + 4);
    tp_acc<O112, 1, 1, 2>(Y + 1, Y + 1, w2[1] * CN2, Z + 4);
    tp_acc<O202, 2, 0, 2>(Y + 4, Y,     w2[2] * CN2, Z + 4);
    tp_acc<O222, 2, 2, 2>(Y + 4, Y + 4, w2[3] * CN2, Z + 4);
    Z[0] += b0 + k[0] * Y[0];
#pragma unroll
    for (int m = 1; m < 4; ++m) Z[m] += k[1] * Y[m];
#pragma unroll
    for (int m = 4; m < 9; ++m) Z[m] += k[2] * Y[m];
}

// ---------------------------------------------------------------------------
// Kernel 1: per-edge selfmix of Y_edge, both branches
// ---------------------------------------------------------------------------
__global__ void zprep_kernel(const float* __restrict__ Y_edge,
                             const float* w0a, const float* w1a, const float* w2a,
                             const float* b0a, const float* ka,
                             const float* w0b, const float* w1b, const float* w2b,
                             const float* b0b, const float* kb, int E) {
    int e = blockIdx.x * blockDim.x + threadIdx.x;
    if (e >= E) return;
    float Y[9];
#pragma unroll
    for (int m = 0; m < 9; ++m) Y[m] = Y_edge[(size_t)e * 9 + m];

    float Z[9];
    {
        float w0[3] = {w0a[0], w0a[1], w0a[2]};
        float w1[4] = {w1a[0], w1a[1], w1a[2], w1a[3]};
        float w2[4] = {w2a[0], w2a[1], w2a[2], w2a[3]};
        float kk[3] = {ka[0], ka[1], ka[2]};
        selfmix1(Y, w0, w1, w2, b0a[0], kk, Z);
        g_Za[(size_t)e * 3 + 0] = make_float4(Z[0], Z[1], Z[2], Z[3]);
        g_Za[(size_t)e * 3 + 1] = make_float4(Z[4], Z[5], Z[6], Z[7]);
        g_Za[(size_t)e * 3 + 2] = make_float4(Z[8], 0.f, 0.f, 0.f);
    }
    {
        float w0[3] = {w0b[0], w0b[1], w0b[2]};
        float w1[4] = {w1b[0], w1b[1], w1b[2], w1b[3]};
        float w2[4] = {w2b[0], w2b[1], w2b[2], w2b[3]};
        float kk[3] = {kb[0], kb[1], kb[2]};
        selfmix1(Y, w0, w1, w2, b0b[0], kk, Z);
        g_Zb[(size_t)e * 3 + 0] = make_float4(Z[0], Z[1], Z[2], Z[3]);
        g_Zb[(size_t)e * 3 + 1] = make_float4(Z[4], Z[5], Z[6], Z[7]);
        g_Zb[(size_t)e * 3 + 2] = make_float4(Z[8], 0.f, 0.f, 0.f);
    }
}

// ---------------------------------------------------------------------------
// Kernel 2: fused main edge kernel — EXACT Round-10 (721.8us) structure.
// Only change: CG coefficients are compile-time immediates (no sCG smem,
// no coefficient LDS in the hot loop).
// smem: WdA 12288 B + WdB 45056 B + staging 4608 B = 61952 B; 3 blocks/SM.
// ---------------------------------------------------------------------------
#define EPW    4
#define TPB    128
#define NWARPS 4
#define SM_WDA 0
#define SM_WDB 3072
#define SM_ST  14336                        // 16B-aligned staging base
#define SM_FLOATS (SM_ST + NWARPS * 288)    // 15488 floats = 61952 B

__device__ __forceinline__ void red_add_v4(float4* addr, float4 v) {
    asm volatile("red.global.add.v4.f32 [%0], {%1,%2,%3,%4};"
                 :: "l"(addr), "f"(v.x), "f"(v.y), "f"(v.z), "f"(v.w)
                 : "memory");
}

__global__ void __launch_bounds__(TPB, 3)
edge_kernel(const float* __restrict__ nodes_snd, const int* __restrict__ edge_ind,
            const float* __restrict__ dist,
            const float* __restrict__ WdA, const float* __restrict__ bdA,
            const float* __restrict__ WdB, const float* __restrict__ bdB,
            const float* __restrict__ cmWa, const float* __restrict__ cmba,
            const float* __restrict__ cmWb, const float* __restrict__ cmbb,
            float* __restrict__ out, int E) {
    extern __shared__ float sm[];
    float* sWdA = sm + SM_WDA;   // [32 f][32 c x 3]
    float* sWdB = sm + SM_WDB;   // [32 f][32 c x 11]
    float* sSt  = sm + SM_ST;    // [NWARPS][288]

    const int tid = threadIdx.x, lane = tid & 31, warp = tid >> 5;

    for (int i = tid; i < 3072;  i += TPB) sWdA[i] = WdA[i];
    for (int i = tid; i < 11264; i += TPB) sWdB[i] = WdB[i];

    // Per-lane (channel) constants
    float bdAr[3], bdBr[11], cma[3], cmbv[3];
#pragma unroll
    for (int l = 0; l < 3; ++l) {
        bdAr[l] = bdA[lane * 3 + l];
        cma[l]  = cmWa[l * 32 + lane];
        cmbv[l] = cmWb[l * 32 + lane];
    }
#pragma unroll
    for (int j = 0; j < 11; ++j) bdBr[j] = bdB[lane * 11 + j];
    const float cba = cmba[lane], cbb = cmbb[lane];
    __syncthreads();

    const int e0 = (blockIdx.x * NWARPS + warp) * EPW;
    if (e0 >= E) return;

    float d[EPW];
#pragma unroll
    for (int k = 0; k < EPW; ++k) {
        int e = e0 + k;
        d[k] = (e < E) ? dist[(size_t)e * 32 + lane] : 0.f;
    }

    float accA[EPW][3], accB[EPW][11];
#pragma unroll
    for (int k = 0; k < EPW; ++k) {
#pragma unroll
        for (int l = 0; l < 3; ++l) accA[k][l] = 0.f;
#pragma unroll
        for (int j = 0; j < 11; ++j) accB[k][j] = 0.f;
    }

    // dist @ Wd: smem column strides 3 / 11 are coprime to 32 -> conflict-free
#pragma unroll 4
    for (int f = 0; f < 32; ++f) {
        float wA[3], wB[11];
#pragma unroll
        for (int l = 0; l < 3; ++l)  wA[l] = sWdA[f * 96 + lane * 3 + l];
#pragma unroll
        for (int j = 0; j < 11; ++j) wB[j] = sWdB[f * 352 + lane * 11 + j];
#pragma unroll
        for (int k = 0; k < EPW; ++k) {
            float df = __shfl_sync(0xffffffffu, d[k], f);
#pragma unroll
            for (int l = 0; l < 3; ++l)  accA[k][l] = fmaf(df, wA[l], accA[k][l]);
#pragma unroll
            for (int j = 0; j < 11; ++j) accB[k][j] = fmaf(df, wB[j], accB[k][j]);
        }
    }

    float*  st  = sSt + warp * 288;
    float4* st4 = reinterpret_cast<float4*>(st);

#pragma unroll 1
    for (int k = 0; k < EPW; ++k) {
        const int e = e0 + k;
        if (e >= E) break;
        const int2 ei = reinterpret_cast<const int2*>(edge_ind)[e];
        const int snd = ei.x, rcv = ei.y;

        // Cooperative coalesced node-row load (1152 B) -> smem -> per-lane read
        const float4* nb4 = reinterpret_cast<const float4*>(
            nodes_snd + (size_t)snd * 288);
        st4[lane]      = nb4[lane];
        st4[32 + lane] = nb4[32 + lane];
        if (lane < 8) st4[64 + lane] = nb4[64 + lane];
        __syncwarp();
        float n[9];
#pragma unroll
        for (int m = 0; m < 9; ++m) n[m] = st[lane * 9 + m];
        __syncwarp();

        // Uniform vector loads of selfmix scratch (lane-invariant broadcast)
        float Za[9], Zb[9];
        {
            float4 z0 = g_Za[(size_t)e * 3 + 0];
            float4 z1 = g_Za[(size_t)e * 3 + 1];
            float4 z2 = g_Za[(size_t)e * 3 + 2];
            Za[0] = z0.x; Za[1] = z0.y; Za[2] = z0.z; Za[3] = z0.w;
            Za[4] = z1.x; Za[5] = z1.y; Za[6] = z1.z; Za[7] = z1.w;
            Za[8] = z2.x;
            z0 = g_Zb[(size_t)e * 3 + 0];
            z1 = g_Zb[(size_t)e * 3 + 1];
            z2 = g_Zb[(size_t)e * 3 + 2];
            Zb[0] = z0.x; Zb[1] = z0.y; Zb[2] = z0.z; Zb[3] = z0.w;
            Zb[4] = z1.x; Zb[5] = z1.y; Zb[6] = z1.z; Zb[7] = z1.w;
            Zb[8] = z2.x;
        }

        // Channel mix (cin = 1): Y[c,m] = Z[m]*W[l(m)][c] (+bias at l=0)
        float Ya[9], Yb[9];
        Ya[0] = fmaf(Za[0], cma[0], cba);
        Yb[0] = fmaf(Zb[0], cmbv[0], cbb);
#pragma unroll
        for (int m = 1; m < 4; ++m) { Ya[m] = Za[m] * cma[1]; Yb[m] = Zb[m] * cmbv[1]; }
#pragma unroll
        for (int m = 4; m < 9; ++m) { Ya[m] = Za[m] * cma[2]; Yb[m] = Zb[m] * cmbv[2]; }

        float wa[3];
#pragma unroll
        for (int l = 0; l < 3; ++l) wa[l] = (accA[k][l] + bdAr[l]) * n[0];
        float wb[11];
#pragma unroll
        for (int j = 0; j < 11; ++j) wb[j] = accB[k][j] + bdBr[j];

        // a-branch message
        float msg[9];
        msg[0] = wa[0] * Ya[0];
#pragma unroll
        for (int m = 1; m < 4; ++m) msg[m] = wa[1] * Ya[m];
#pragma unroll
        for (int m = 4; m < 9; ++m) msg[m] = wa[2] * Ya[m];

        // b-branch: pair_mix(neighbors, Yb, wb) with immediate CG
        tp_acc<O000, 0, 0, 0>(n,     Yb,     wb[0]  * CN0, msg);
        tp_acc<O110, 1, 1, 0>(n + 1, Yb + 1, wb[1]  * CN0, msg);
        tp_acc<O220, 2, 2, 0>(n + 4, Yb + 4, wb[2]  * CN0, msg);
        tp_acc<O011, 0, 1, 1>(n,     Yb + 1, wb[3]  * CN1, msg + 1);
        tp_acc<O101, 1, 0, 1>(n + 1, Yb,     wb[4]  * CN1, msg + 1);
        tp_acc<O121, 1, 2, 1>(n + 1, Yb + 4, wb[5]  * CN1, msg + 1);
        tp_acc<O211, 2, 1, 1>(n + 4, Yb + 1, wb[6]  * CN1, msg + 1);
        tp_acc<O022, 0, 2, 2>(n,     Yb + 4, wb[7]  * CN2, msg + 4);
        tp_acc<O112, 1, 1, 2>(n + 1, Yb + 1, wb[8]  * CN2, msg + 4);
        tp_acc<O202, 2, 0, 2>(n + 4, Yb,     wb[9]  * CN2, msg + 4);
        tp_acc<O222, 2, 2, 2>(n + 4, Yb + 4, wb[10] * CN2, msg + 4);

        // Transpose via smem, then coalesced float4 vector atomics.
        // Row base rcv*288 floats = 1152 B -> 128B-aligned.
#pragma unroll
        for (int m = 0; m < 9; ++m) st[lane * 9 + m] = msg[m];
        __syncwarp();
        float4* dst = reinterpret_cast<float4*>(out + (size_t)rcv * 288);
        red_add_v4(dst + lane,      st4[lane]);
        red_add_v4(dst + 32 + lane, st4[32 + lane]);
        if (lane < 8) red_add_v4(dst + 64 + lane, st4[64 + lane]);
        __syncwarp();
    }
}

// ---------------------------------------------------------------------------
// kernel_launch
// ---------------------------------------------------------------------------
extern "C" void kernel_launch(void* const* d_in, const int* in_sizes, int n_in,
                              void* d_out, int out_size) {
    const float* nodes_rec = (const float*)d_in[0];
    const float* nodes_snd = (const float*)d_in[1];
    const int*   edge_ind  = (const int*)d_in[2];
    const float* Y_edge    = (const float*)d_in[3];
    const float* dist      = (const float*)d_in[4];
    const int E = in_sizes[2] / 2;

    // Detect parameter ordering: signature order has Wd_a (3072) at index 12.
    int iA0, iB0, iWdA, ibdA, iWdB, ibdB;
    if (in_sizes[12] >= 3000) {  // signature order
        iA0 = 5;  iWdA = 12; ibdA = 13;
        iB0 = 14; iWdB = 21; ibdB = 22;
    } else {                     // dict order
        iA0 = 5;  iB0 = 12;
        iWdA = 19; ibdA = 20; iWdB = 21; ibdB = 22;
    }
    const float* sm_a_w0 = (const float*)d_in[iA0 + 0];
    const float* sm_a_w1 = (const float*)d_in[iA0 + 1];
    const float* sm_a_w2 = (const float*)d_in[iA0 + 2];
    const float* sm_a_b0 = (const float*)d_in[iA0 + 3];
    const float* sm_a_k  = (const float*)d_in[iA0 + 4];
    const float* cm_a_W  = (const float*)d_in[iA0 + 5];
    const float* cm_a_b  = (const float*)d_in[iA0 + 6];
    const float* sm_b_w0 = (const float*)d_in[iB0 + 0];
    const float* sm_b_w1 = (const float*)d_in[iB0 + 1];
    const float* sm_b_w2 = (const float*)d_in[iB0 + 2];
    const float* sm_b_b0 = (const float*)d_in[iB0 + 3];
    const float* sm_b_k  = (const float*)d_in[iB0 + 4];
    const float* cm_b_W  = (const float*)d_in[iB0 + 5];
    const float* cm_b_b  = (const float*)d_in[iB0 + 6];
    const float* Wd_a    = (const float*)d_in[iWdA];
    const float* bd_a    = (const float*)d_in[ibdA];
    const float* Wd_b    = (const float*)d_in[iWdB];
    const float* bd_b    = (const float*)d_in[ibdB];

    float* out = (float*)d_out;

    // out starts as nodes_rec; atomics accumulate messages on top.
    cudaMemcpyAsync(out, nodes_rec, (size_t)out_size * sizeof(float),
                    cudaMemcpyDeviceToDevice, 0);

    zprep_kernel<<<(E + 255) / 256, 256, 0, 0>>>(
        Y_edge, sm_a_w0, sm_a_w1, sm_a_w2, sm_a_b0, sm_a_k,
        sm_b_w0, sm_b_w1, sm_b_w2, sm_b_b0, sm_b_k, E);

    static bool attr_set = false;
    if (!attr_set) {
        cudaFuncSetAttribute(edge_kernel,
                             cudaFuncAttributeMaxDynamicSharedMemorySize,
                             SM_FLOATS * 4);
        attr_set = true;
    }
    int blocks = (E + NWARPS * EPW - 1) / (NWARPS * EPW);
    edge_kernel<<<blocks, TPB, SM_FLOATS * 4, 0>>>(
        nodes_snd, edge_ind, dist,
        Wd_a, bd_a, Wd_b, bd_b,
        cm_a_W, cm_a_b, cm_b_W, cm_b_b,
        out, E);
}

// round 16
// speedup vs baseline: 1.7515x; 1.1767x over previous
#include <cuda_runtime.h>
#include <math.h>

// ---------------------------------------------------------------------------
// Problem constants / scratch
// ---------------------------------------------------------------------------
#define MAX_E 256000

// Per-edge selfmix scratch, padded to 12 floats/edge for float4 access.
__device__ float4 g_Za[MAX_E * 3];
__device__ float4 g_Zb[MAX_E * 3];

// sqrt(2*l3+1)/sqrt(npaths(l3))
#define CN0 0.57735026918962576f
#define CN1 0.86602540378443865f
#define CN2 1.11803398874989485f

// ---------------------------------------------------------------------------
// Compile-time real Clebsch-Gordan construction (constexpr port of reference)
// ---------------------------------------------------------------------------
struct CD { double re, im; };
constexpr CD cmul(CD a, CD b) { return {a.re*b.re - a.im*b.im, a.re*b.im + a.im*b.re}; }
constexpr CD cmulr(CD a, double s) { return {a.re*s, a.im*s}; }
constexpr CD cadd(CD a, CD b) { return {a.re + b.re, a.im + b.im}; }

constexpr double cfabs(double x) { return x < 0 ? -x : x; }
constexpr double csqrt_(double x) {
    if (x <= 0.0) return 0.0;
    double g = x < 1.0 ? 1.0 : x;
    for (int i = 0; i < 200; ++i) g = 0.5 * (g + x / g);
    return g;
}
constexpr double factc(int n) { double r = 1.0; for (int i = 2; i <= n; ++i) r *= i; return r; }

constexpr double w3j_c(int j1, int j2, int j3, int m1, int m2, int m3) {
    if (m1 + m2 + m3 != 0) return 0.0;
    int lo = j1 - j2; if (lo < 0) lo = -lo;
    if (j3 < lo || j3 > j1 + j2) return 0.0;
    int t1 = j2 - m1 - j3, t2 = j1 + m2 - j3, t3 = j1 + j2 - j3;
    int t4 = j1 - m1, t5 = j2 + m2;
    int tmin = 0; if (t1 > tmin) tmin = t1; if (t2 > tmin) tmin = t2;
    int tmax = t3; if (t4 < tmax) tmax = t4; if (t5 < tmax) tmax = t5;
    double s = 0.0;
    for (int t = tmin; t <= tmax; ++t)
        s += ((t & 1) ? -1.0 : 1.0) /
             (factc(t) * factc(t - t1) * factc(t - t2) *
              factc(t3 - t) * factc(t4 - t) * factc(t5 - t));
    double delta = factc(j1 + j2 - j3) * factc(j1 - j2 + j3) *
                   factc(-j1 + j2 + j3) / factc(j1 + j2 + j3 + 1);
    double norm = csqrt_(delta * factc(j1 + m1) * factc(j1 - m1) *
                         factc(j2 + m2) * factc(j2 - m2) *
                         factc(j3 + m3) * factc(j3 - m3));
    int e = j1 - j2 - m3;
    double sgn = (((e % 2) + 2) % 2) ? -1.0 : 1.0;
    return sgn * norm * s;
}

struct U55 { CD u[5][5]; };
constexpr U55 u_real_c(int l) {
    U55 U{};
    U.u[l][l] = {1.0, 0.0};
    double s2 = 1.0 / csqrt_(2.0);
    for (int m = 1; m <= l; ++m) {
        double sg = (m & 1) ? -1.0 : 1.0;
        U.u[l + m][l + m] = {sg * s2, 0.0};
        U.u[l + m][l - m] = {s2, 0.0};
        U.u[l - m][l + m] = {0.0, -sg * s2};
        U.u[l - m][l - m] = {0.0, s2};
    }
    return U;
}

struct CGAll { float cg[363]; };
constexpr CGAll build_cg_c() {
    CGAll R{};
    const int pl[11][3] = {{0,0,0},{1,1,0},{2,2,0},
                           {0,1,1},{1,0,1},{1,2,1},{2,1,1},
                           {0,2,2},{1,1,2},{2,0,2},{2,2,2}};
    int off = 0;
    for (int p = 0; p < 11; ++p) {
        int l1 = pl[p][0], l2 = pl[p][1], l3 = pl[p][2];
        int d1 = 2*l1+1, d2 = 2*l2+1, d3 = 2*l3+1;
        double W[5][5][5] = {};
        for (int m1 = -l1; m1 <= l1; ++m1)
            for (int m2 = -l2; m2 <= l2; ++m2) {
                int m3 = -(m1 + m2);
                if (m3 >= -l3 && m3 <= l3)
                    W[l1 + m1][l2 + m2][l3 + m3] = w3j_c(l1, l2, l3, m1, m2, m3);
            }
        U55 U1 = u_real_c(l1), U2 = u_real_c(l2), U3 = u_real_c(l3);
        double Tre[5][5][5] = {}, Tim[5][5][5] = {};
        double mxr = 0.0, mxi = 0.0;
        for (int a = 0; a < d1; ++a)
            for (int b = 0; b < d2; ++b)
                for (int c = 0; c < d3; ++c) {
                    CD s = {0.0, 0.0};
                    for (int m = 0; m < d1; ++m) {
                        if (U1.u[a][m].re == 0.0 && U1.u[a][m].im == 0.0) continue;
                        for (int n = 0; n < d2; ++n) {
                            if (U2.u[b][n].re == 0.0 && U2.u[b][n].im == 0.0) continue;
                            for (int o = 0; o < d3; ++o) {
                                if (W[m][n][o] == 0.0) continue;
                                s = cadd(s, cmulr(cmul(cmul(U1.u[a][m], U2.u[b][n]),
                                                       U3.u[c][o]), W[m][n][o]));
                            }
                        }
                    }
                    Tre[a][b][c] = s.re; Tim[a][b][c] = s.im;
                    if (cfabs(s.re) > mxr) mxr = cfabs(s.re);
                    if (cfabs(s.im) > mxi) mxi = cfabs(s.im);
                }
        bool useRe = (mxr >= mxi);
        for (int a = 0; a < d1; ++a)
            for (int b = 0; b < d2; ++b)
                for (int c = 0; c < d3; ++c)
                    R.cg[off + (a * d2 + b) * d3 + c] =
                        (float)(useRe ? Tre[a][b][c] : Tim[a][b][c]);
        off += d1 * d2 * d3;
    }
    return R;
}
constexpr CGAll CGC = build_cg_c();

#define O000 0
#define O110 1
#define O220 10
#define O011 35
#define O101 44
#define O121 53
#define O211 98
#define O022 143
#define O112 168
#define O202 213
#define O222 238

// ---------------------------------------------------------------------------
// Tensor product with CG as compile-time immediates (exact-sparsity DCE).
// ---------------------------------------------------------------------------
template <int OFF, int L2, int L3, int A, int B, int C = 0>
__device__ __forceinline__ void tp_cs(float p, float* zp) {
    if constexpr (C < 2 * L3 + 1) {
        constexpr float g = CGC.cg[OFF + (A * (2 * L2 + 1) + B) * (2 * L3 + 1) + C];
        if constexpr (g != 0.0f) zp[C] = fmaf(g, p, zp[C]);
        tp_cs<OFF, L2, L3, A, B, C + 1>(p, zp);
    }
}
template <int OFF, int L1, int L2, int L3, int A = 0, int B = 0>
__device__ __forceinline__ void tp_ab(const float* x, const float* y, float* zp) {
    if constexpr (B < 2 * L2 + 1) {
        float p = x[A] * y[B];
        tp_cs<OFF, L2, L3, A, B, 0>(p, zp);
        tp_ab<OFF, L1, L2, L3, A, B + 1>(x, y, zp);
    } else if constexpr (A + 1 < 2 * L1 + 1) {
        tp_ab<OFF, L1, L2, L3, A + 1, 0>(x, y, zp);
    }
}
template <int OFF, int L1, int L2, int L3>
__device__ __forceinline__ void tp_acc(const float* x, const float* y,
                                       float w, float* z) {
    float zp[2 * L3 + 1];
#pragma unroll
    for (int c = 0; c < 2 * L3 + 1; ++c) zp[c] = 0.f;
    tp_ab<OFF, L1, L2, L3, 0, 0>(x, y, zp);
#pragma unroll
    for (int c = 0; c < 2 * L3 + 1; ++c) z[c] = fmaf(w, zp[c], z[c]);
}

// Selfmix on one 9-vector (cin = 1)
__device__ __forceinline__ void selfmix1(const float* Y,
                                         const float* w0, const float* w1,
                                         const float* w2, float b0,
                                         const float* k, float* Z) {
#pragma unroll
    for (int m = 0; m < 9; ++m) Z[m] = 0.f;
    tp_acc<O000, 0, 0, 0>(Y,     Y,     w0[0] * CN0, Z);
    tp_acc<O110, 1, 1, 0>(Y + 1, Y + 1, w0[1] * CN0, Z);
    tp_acc<O220, 2, 2, 0>(Y + 4, Y + 4, w0[2] * CN0, Z);
    tp_acc<O011, 0, 1, 1>(Y,     Y + 1, w1[0] * CN1, Z + 1);
    tp_acc<O101, 1, 0, 1>(Y + 1, Y,     w1[1] * CN1, Z + 1);
    tp_acc<O121, 1, 2, 1>(Y + 1, Y + 4, w1[2] * CN1, Z + 1);
    tp_acc<O211, 2, 1, 1>(Y + 4, Y + 1, w1[3] * CN1, Z + 1);
    tp_acc<O022, 0, 2, 2>(Y,     Y + 4, w2[0] * CN2, Z + 4);
    tp_acc<O112, 1, 1, 2>(Y + 1, Y + 1, w2[1] * CN2, Z + 4);
    tp_acc<O202, 2, 0, 2>(Y + 4, Y,     w2[2] * CN2, Z + 4);
    tp_acc<O222, 2, 2, 2>(Y + 4, Y + 4, w2[3] * CN2, Z + 4);
    Z[0] += b0 + k[0] * Y[0];
#pragma unroll
    for (int m = 1; m < 4; ++m) Z[m] += k[1] * Y[m];
#pragma unroll
    for (int m = 4; m < 9; ++m) Z[m] += k[2] * Y[m];
}

// ---------------------------------------------------------------------------
// Kernel 1: per-edge selfmix of Y_edge, both branches
// ---------------------------------------------------------------------------
__global__ void zprep_kernel(const float* __restrict__ Y_edge,
                             const float* w0a, const float* w1a, const float* w2a,
                             const float* b0a, const float* ka,
                             const float* w0b, const float* w1b, const float* w2b,
                             const float* b0b, const float* kb, int E) {
    int e = blockIdx.x * blockDim.x + threadIdx.x;
    if (e >= E) return;
    float Y[9];
#pragma unroll
    for (int m = 0; m < 9; ++m) Y[m] = Y_edge[(size_t)e * 9 + m];

    float Z[9];
    {
        float w0[3] = {w0a[0], w0a[1], w0a[2]};
        float w1[4] = {w1a[0], w1a[1], w1a[2], w1a[3]};
        float w2[4] = {w2a[0], w2a[1], w2a[2], w2a[3]};
        float kk[3] = {ka[0], ka[1], ka[2]};
        selfmix1(Y, w0, w1, w2, b0a[0], kk, Z);
        g_Za[(size_t)e * 3 + 0] = make_float4(Z[0], Z[1], Z[2], Z[3]);
        g_Za[(size_t)e * 3 + 1] = make_float4(Z[4], Z[5], Z[6], Z[7]);
        g_Za[(size_t)e * 3 + 2] = make_float4(Z[8], 0.f, 0.f, 0.f);
    }
    {
        float w0[3] = {w0b[0], w0b[1], w0b[2]};
        float w1[4] = {w1b[0], w1b[1], w1b[2], w1b[3]};
        float w2[4] = {w2b[0], w2b[1], w2b[2], w2b[3]};
        float kk[3] = {kb[0], kb[1], kb[2]};
        selfmix1(Y, w0, w1, w2, b0b[0], kk, Z);
        g_Zb[(size_t)e * 3 + 0] = make_float4(Z[0], Z[1], Z[2], Z[3]);
        g_Zb[(size_t)e * 3 + 1] = make_float4(Z[4], Z[5], Z[6], Z[7]);
        g_Zb[(size_t)e * 3 + 2] = make_float4(Z[8], 0.f, 0.f, 0.f);
    }
}

// ---------------------------------------------------------------------------
// Kernel 2: PERSISTENT fused edge kernel. Warp = EPW edges per iteration,
// grid-stride loop over edge groups: weights staged ONCE per block instead
// of once per 16 edges (R15 analysis: 917 MB L2 weight re-traffic, ~2-3K cyc
// staging x 108 sequential blocks/SM was the hidden fixed cost).
// Loop body = exact R10 structure with CG immediates.
// ---------------------------------------------------------------------------
#define EPW    4
#define TPB    128
#define NWARPS 4
#define NBLOCKS (148 * 3)
#define SM_WDA 0
#define SM_WDB 3072
#define SM_ST  14336                        // 16B-aligned staging base
#define SM_FLOATS (SM_ST + NWARPS * 288)    // 15488 floats = 61952 B

__device__ __forceinline__ void red_add_v4(float4* addr, float4 v) {
    asm volatile("red.global.add.v4.f32 [%0], {%1,%2,%3,%4};"
                 :: "l"(addr), "f"(v.x), "f"(v.y), "f"(v.z), "f"(v.w)
                 : "memory");
}

__global__ void __launch_bounds__(TPB, 3)
edge_kernel(const float* __restrict__ nodes_snd, const int* __restrict__ edge_ind,
            const float* __restrict__ dist,
            const float* __restrict__ WdA, const float* __restrict__ bdA,
            const float* __restrict__ WdB, const float* __restrict__ bdB,
            const float* __restrict__ cmWa, const float* __restrict__ cmba,
            const float* __restrict__ cmWb, const float* __restrict__ cmbb,
            float* __restrict__ out, int E) {
    extern __shared__ float sm[];
    float* sWdA = sm + SM_WDA;   // [32 f][32 c x 3]
    float* sWdB = sm + SM_WDB;   // [32 f][32 c x 11]
    float* sSt  = sm + SM_ST;    // [NWARPS][288]

    const int tid = threadIdx.x, lane = tid & 31, warp = tid >> 5;

    // Stage weights ONCE per (persistent) block
    for (int i = tid; i < 3072;  i += TPB) sWdA[i] = WdA[i];
    for (int i = tid; i < 11264; i += TPB) sWdB[i] = WdB[i];

    // Per-lane (channel) constants — loaded once
    float bdAr[3], bdBr[11], cma[3], cmbv[3];
#pragma unroll
    for (int l = 0; l < 3; ++l) {
        bdAr[l] = bdA[lane * 3 + l];
        cma[l]  = cmWa[l * 32 + lane];
        cmbv[l] = cmWb[l * 32 + lane];
    }
#pragma unroll
    for (int j = 0; j < 11; ++j) bdBr[j] = bdB[lane * 11 + j];
    const float cba = cmba[lane], cbb = cmbb[lane];
    __syncthreads();

    float*  st  = sSt + warp * 288;
    float4* st4 = reinterpret_cast<float4*>(st);

    const int gstride = NBLOCKS * NWARPS * EPW;

    for (int e0 = (blockIdx.x * NWARPS + warp) * EPW; e0 < E; e0 += gstride) {

        float d[EPW];
#pragma unroll
        for (int k = 0; k < EPW; ++k) {
            int e = e0 + k;
            d[k] = (e < E) ? dist[(size_t)e * 32 + lane] : 0.f;
        }

        float accA[EPW][3], accB[EPW][11];
#pragma unroll
        for (int k = 0; k < EPW; ++k) {
#pragma unroll
            for (int l = 0; l < 3; ++l) accA[k][l] = 0.f;
#pragma unroll
            for (int j = 0; j < 11; ++j) accB[k][j] = 0.f;
        }

        // dist @ Wd: smem strides 3 / 11 coprime to 32 -> conflict-free
#pragma unroll 4
        for (int f = 0; f < 32; ++f) {
            float wA[3], wB[11];
#pragma unroll
            for (int l = 0; l < 3; ++l)  wA[l] = sWdA[f * 96 + lane * 3 + l];
#pragma unroll
            for (int j = 0; j < 11; ++j) wB[j] = sWdB[f * 352 + lane * 11 + j];
#pragma unroll
            for (int k = 0; k < EPW; ++k) {
                float df = __shfl_sync(0xffffffffu, d[k], f);
#pragma unroll
                for (int l = 0; l < 3; ++l)  accA[k][l] = fmaf(df, wA[l], accA[k][l]);
#pragma unroll
                for (int j = 0; j < 11; ++j) accB[k][j] = fmaf(df, wB[j], accB[k][j]);
            }
        }

#pragma unroll 1
        for (int k = 0; k < EPW; ++k) {
            const int e = e0 + k;
            if (e >= E) break;
            const int2 ei = reinterpret_cast<const int2*>(edge_ind)[e];
            const int snd = ei.x, rcv = ei.y;

            // Cooperative coalesced node-row load -> smem -> per-lane read
            const float4* nb4 = reinterpret_cast<const float4*>(
                nodes_snd + (size_t)snd * 288);
            st4[lane]      = nb4[lane];
            st4[32 + lane] = nb4[32 + lane];
            if (lane < 8) st4[64 + lane] = nb4[64 + lane];
            __syncwarp();
            float n[9];
#pragma unroll
            for (int m = 0; m < 9; ++m) n[m] = st[lane * 9 + m];
            __syncwarp();

            // Uniform vector loads of selfmix scratch (broadcast)
            float Za[9], Zb[9];
            {
                float4 z0 = g_Za[(size_t)e * 3 + 0];
                float4 z1 = g_Za[(size_t)e * 3 + 1];
                float4 z2 = g_Za[(size_t)e * 3 + 2];
                Za[0] = z0.x; Za[1] = z0.y; Za[2] = z0.z; Za[3] = z0.w;
                Za[4] = z1.x; Za[5] = z1.y; Za[6] = z1.z; Za[7] = z1.w;
                Za[8] = z2.x;
                z0 = g_Zb[(size_t)e * 3 + 0];
                z1 = g_Zb[(size_t)e * 3 + 1];
                z2 = g_Zb[(size_t)e * 3 + 2];
                Zb[0] = z0.x; Zb[1] = z0.y; Zb[2] = z0.z; Zb[3] = z0.w;
                Zb[4] = z1.x; Zb[5] = z1.y; Zb[6] = z1.z; Zb[7] = z1.w;
                Zb[8] = z2.x;
            }

            // Channel mix (cin = 1)
            float Ya[9], Yb[9];
            Ya[0] = fmaf(Za[0], cma[0], cba);
            Yb[0] = fmaf(Zb[0], cmbv[0], cbb);
#pragma unroll
            for (int m = 1; m < 4; ++m) { Ya[m] = Za[m] * cma[1]; Yb[m] = Zb[m] * cmbv[1]; }
#pragma unroll
            for (int m = 4; m < 9; ++m) { Ya[m] = Za[m] * cma[2]; Yb[m] = Zb[m] * cmbv[2]; }

            float wa[3];
#pragma unroll
            for (int l = 0; l < 3; ++l) wa[l] = (accA[k][l] + bdAr[l]) * n[0];
            float wb[11];
#pragma unroll
            for (int j = 0; j < 11; ++j) wb[j] = accB[k][j] + bdBr[j];

            // a-branch message
            float msg[9];
            msg[0] = wa[0] * Ya[0];
#pragma unroll
            for (int m = 1; m < 4; ++m) msg[m] = wa[1] * Ya[m];
#pragma unroll
            for (int m = 4; m < 9; ++m) msg[m] = wa[2] * Ya[m];

            // b-branch: pair_mix(neighbors, Yb, wb) with immediate CG
            tp_acc<O000, 0, 0, 0>(n,     Yb,     wb[0]  * CN0, msg);
            tp_acc<O110, 1, 1, 0>(n + 1, Yb + 1, wb[1]  * CN0, msg);
            tp_acc<O220, 2, 2, 0>(n + 4, Yb + 4, wb[2]  * CN0, msg);
            tp_acc<O011, 0, 1, 1>(n,     Yb + 1, wb[3]  * CN1, msg + 1);
            tp_acc<O101, 1, 0, 1>(n + 1, Yb,     wb[4]  * CN1, msg + 1);
            tp_acc<O121, 1, 2, 1>(n + 1, Yb + 4, wb[5]  * CN1, msg + 1);
            tp_acc<O211, 2, 1, 1>(n + 4, Yb + 1, wb[6]  * CN1, msg + 1);
            tp_acc<O022, 0, 2, 2>(n,     Yb + 4, wb[7]  * CN2, msg + 4);
            tp_acc<O112, 1, 1, 2>(n + 1, Yb + 1, wb[8]  * CN2, msg + 4);
            tp_acc<O202, 2, 0, 2>(n + 4, Yb,     wb[9]  * CN2, msg + 4);
            tp_acc<O222, 2, 2, 2>(n + 4, Yb + 4, wb[10] * CN2, msg + 4);

            // Transpose via smem, then coalesced float4 vector atomics.
#pragma unroll
            for (int m = 0; m < 9; ++m) st[lane * 9 + m] = msg[m];
            __syncwarp();
            float4* dst = reinterpret_cast<float4*>(out + (size_t)rcv * 288);
            red_add_v4(dst + lane,      st4[lane]);
            red_add_v4(dst + 32 + lane, st4[32 + lane]);
            if (lane < 8) red_add_v4(dst + 64 + lane, st4[64 + lane]);
            __syncwarp();
        }
    }
}

// ---------------------------------------------------------------------------
// kernel_launch
// ---------------------------------------------------------------------------
extern "C" void kernel_launch(void* const* d_in, const int* in_sizes, int n_in,
                              void* d_out, int out_size) {
    const float* nodes_rec = (const float*)d_in[0];
    const float* nodes_snd = (const float*)d_in[1];
    const int*   edge_ind  = (const int*)d_in[2];
    const float* Y_edge    = (const float*)d_in[3];
    const float* dist      = (const float*)d_in[4];
    const int E = in_sizes[2] / 2;

    // Detect parameter ordering: signature order has Wd_a (3072) at index 12.
    int iA0, iB0, iWdA, ibdA, iWdB, ibdB;
    if (in_sizes[12] >= 3000) {  // signature order
        iA0 = 5;  iWdA = 12; ibdA = 13;
        iB0 = 14; iWdB = 21; ibdB = 22;
    } else {                     // dict order
        iA0 = 5;  iB0 = 12;
        iWdA = 19; ibdA = 20; iWdB = 21; ibdB = 22;
    }
    const float* sm_a_w0 = (const float*)d_in[iA0 + 0];
    const float* sm_a_w1 = (const float*)d_in[iA0 + 1];
    const float* sm_a_w2 = (const float*)d_in[iA0 + 2];
    const float* sm_a_b0 = (const float*)d_in[iA0 + 3];
    const float* sm_a_k  = (const float*)d_in[iA0 + 4];
    const float* cm_a_W  = (const float*)d_in[iA0 + 5];
    const float* cm_a_b  = (const float*)d_in[iA0 + 6];
    const float* sm_b_w0 = (const float*)d_in[iB0 + 0];
    const float* sm_b_w1 = (const float*)d_in[iB0 + 1];
    const float* sm_b_w2 = (const float*)d_in[iB0 + 2];
    const float* sm_b_b0 = (const float*)d_in[iB0 + 3];
    const float* sm_b_k  = (const float*)d_in[iB0 + 4];
    const float* cm_b_W  = (const float*)d_in[iB0 + 5];
    const float* cm_b_b  = (const float*)d_in[iB0 + 6];
    const float* Wd_a    = (const float*)d_in[iWdA];
    const float* bd_a    = (const float*)d_in[ibdA];
    const float* Wd_b    = (const float*)d_in[iWdB];
    const float* bd_b    = (const float*)d_in[ibdB];

    float* out = (float*)d_out;

    // out starts as nodes_rec; atomics accumulate messages on top.
    cudaMemcpyAsync(out, nodes_rec, (size_t)out_size * sizeof(float),
                    cudaMemcpyDeviceToDevice, 0);

    zprep_kernel<<<(E + 255) / 256, 256, 0, 0>>>(
        Y_edge, sm_a_w0, sm_a_w1, sm_a_w2, sm_a_b0, sm_a_k,
        sm_b_w0, sm_b_w1, sm_b_w2, sm_b_b0, sm_b_k, E);

    static bool attr_set = false;
    if (!attr_set) {
        cudaFuncSetAttribute(edge_kernel,
                             cudaFuncAttributeMaxDynamicSharedMemorySize,
                             SM_FLOATS * 4);
        attr_set = true;
    }
    edge_kernel<<<NBLOCKS, TPB, SM_FLOATS * 4, 0>>>(
        nodes_snd, edge_ind, dist,
        Wd_a, bd_a, Wd_b, bd_b,
        cm_a_W, cm_a_b, cm_b_W, cm_b_b,
        out, E);
}